// round 13
// baseline (speedup 1.0000x reference)
#include <cuda_runtime.h>
#include <cuda_fp16.h>
#include <cstdint>

// ---------------------------------------------------------------------------
// Problem constants
// ---------------------------------------------------------------------------
#define M_DIM 8192      // 4*2048
#define N_DIM 11008
#define K_DIM 4096
#define NGROUPS 32
#define BM 128
#define BN 128
#define BK 64
#define THREADS 128     // 4 warps: 2 (M) x 2 (N), warp tile 64x64
#define T_ITERS (K_DIM / BK)   // 64
#define NSTAGES 3

// Stage: A tile 16KB + B tile 16KB (128 rows x 128B, XOR-swizzled)
#define OFF_B       16384
#define STAGE_BYTES 32768
#define SMEM_TOTAL  (NSTAGES * STAGE_BYTES)   // 96KB -> 2 CTAs/SM

// Scratch: dequantized fp16 operands (static device globals; no runtime alloc)
__device__ __half g_A[(size_t)M_DIM * K_DIM];   // x as fp16, row-major [M,K]
__device__ __half g_B[(size_t)N_DIM * K_DIM];   // W as fp16, row-major [N,K]
__device__ int g_w_wide;

static __device__ __forceinline__ uint32_t pack2(__half a, __half b) {
    __half2 h = __halves2half2(a, b);
    return *reinterpret_cast<uint32_t*>(&h);
}

// ---------------------------------------------------------------------------
// Pre-pass kernels (unchanged)
// ---------------------------------------------------------------------------
__global__ void detect_kernel(const int* __restrict__ w) {
    __shared__ int any_big;
    if (threadIdx.x == 0) any_big = 0;
    __syncthreads();
    int big = 0;
    for (int i = threadIdx.x; i < 4096; i += blockDim.x) {
        int v = w[i];
        if (v > 127 || v < -128) big = 1;
    }
    if (big) any_big = 1;
    __syncthreads();
    if (threadIdx.x == 0) g_w_wide = any_big ? 0 : 1;
}

__global__ void convert_x_kernel(const float* __restrict__ x) {
    size_t i = (size_t)blockIdx.x * blockDim.x + threadIdx.x;
    if (i >= (size_t)M_DIM * K_DIM / 8) return;
    const float4* p = reinterpret_cast<const float4*>(x) + i * 2;
    float4 u = p[0];
    float4 v = p[1];
    uint4 o;
    o.x = pack2(__float2half_rn(u.x), __float2half_rn(u.y));
    o.y = pack2(__float2half_rn(u.z), __float2half_rn(u.w));
    o.z = pack2(__float2half_rn(v.x), __float2half_rn(v.y));
    o.w = pack2(__float2half_rn(v.z), __float2half_rn(v.w));
    reinterpret_cast<uint4*>(g_A)[i] = o;
}

__global__ void dequant_w_kernel(const void* __restrict__ wq,
                                 const float* __restrict__ scales) {
    size_t i = (size_t)blockIdx.x * blockDim.x + threadIdx.x;
    if (i >= (size_t)N_DIM * K_DIM / 8) return;
    size_t kc = i % (K_DIM / 8);
    size_t n  = i / (K_DIM / 8);
    float s = scales[n * NGROUPS + (kc >> 4)];
    int q[8];
    if (g_w_wide) {
        const int4* p = reinterpret_cast<const int4*>(wq) + i * 2;
        int4 a = p[0];
        int4 b = p[1];
        q[0] = a.x; q[1] = a.y; q[2] = a.z; q[3] = a.w;
        q[4] = b.x; q[5] = b.y; q[6] = b.z; q[7] = b.w;
    } else {
        int2 w = reinterpret_cast<const int2*>(wq)[i];
#pragma unroll
        for (int b = 0; b < 4; b++) {
            q[b]     = (int)(int8_t)(w.x >> (8 * b));
            q[b + 4] = (int)(int8_t)(w.y >> (8 * b));
        }
    }
    __half h[8];
#pragma unroll
    for (int j = 0; j < 8; j++) h[j] = __float2half_rn((float)q[j] * s);
    uint4 o;
    o.x = pack2(h[0], h[1]);
    o.y = pack2(h[2], h[3]);
    o.z = pack2(h[4], h[5]);
    o.w = pack2(h[6], h[7]);
    reinterpret_cast<uint4*>(g_B)[i] = o;
}

// ---------------------------------------------------------------------------
// GEMM: C = A * B^T, fp16 mma.sync, fp32 acc; epilogue fp16(acc)+fp16(bias).
// 128x128x64 tile, 128 threads (4 warps, 2x2), warp tile 64x64, 2 CTAs/SM.
// BOTH A and B fragments double-buffered across ks steps: in steady state
// every ldsm has a full ks-step of MMA issue to complete -> no RAW exposure.
// ---------------------------------------------------------------------------
__device__ __forceinline__ void cp_async16(uint32_t dst, const void* src) {
    asm volatile("cp.async.cg.shared.global [%0], [%1], 16;\n" ::"r"(dst), "l"(src));
}
#define CP_COMMIT() asm volatile("cp.async.commit_group;\n")
#define CP_WAIT1()  asm volatile("cp.async.wait_group 1;\n")

__device__ __forceinline__ void ldsm_x4(uint32_t& r0, uint32_t& r1, uint32_t& r2,
                                        uint32_t& r3, uint32_t addr) {
    asm volatile("ldmatrix.sync.aligned.m8n8.x4.shared.b16 {%0,%1,%2,%3}, [%4];\n"
                 : "=r"(r0), "=r"(r1), "=r"(r2), "=r"(r3)
                 : "r"(addr));
}
__device__ __forceinline__ void mma_16816(float* c, const uint32_t* a,
                                          uint32_t b0, uint32_t b1) {
    asm volatile(
        "mma.sync.aligned.m16n8k16.row.col.f32.f16.f16.f32 "
        "{%0,%1,%2,%3},{%4,%5,%6,%7},{%8,%9},{%0,%1,%2,%3};\n"
        : "+f"(c[0]), "+f"(c[1]), "+f"(c[2]), "+f"(c[3])
        : "r"(a[0]), "r"(a[1]), "r"(a[2]), "r"(a[3]), "r"(b0), "r"(b1));
}

// Swizzled smem byte offset: row r (128B rows), 16B-chunk c
__device__ __forceinline__ uint32_t sw_off(int r, int c) {
    return (uint32_t)(r * 128 + ((c ^ (r & 7)) << 4));
}

__global__ void __launch_bounds__(THREADS, 2)
gemm_kernel(const float* __restrict__ bias, float* __restrict__ out) {
    extern __shared__ char smem[];
    const int tid  = threadIdx.x;
    const int lane = tid & 31;
    const int warp = tid >> 5;
    const int wm = warp >> 1;       // 0..1 (M: 64 rows each)
    const int wn = warp & 1;        // 0..1 (N: 64 cols each)
    const int bM = blockIdx.y * BM;
    const int bN = blockIdx.x * BN;

    const uint32_t smem_base = (uint32_t)__cvta_generic_to_shared(smem);

    float acc[4][8][4];
#pragma unroll
    for (int i = 0; i < 4; i++)
#pragma unroll
        for (int j = 0; j < 8; j++)
#pragma unroll
            for (int k = 0; k < 4; k++) acc[i][j][k] = 0.f;

    // Precompute fragment-row smem offsets and swizzle phases (loop-invariant)
    const int lr = lane & 15;
    const int lc = lane >> 4;
    uint32_t aoff[4], boff[4];
    int aph[4], bph[4];
#pragma unroll
    for (int mt = 0; mt < 4; mt++) {
        int r = wm * 64 + mt * 16 + lr;
        aoff[mt] = (uint32_t)(r * 128);
        aph[mt]  = r & 7;
    }
#pragma unroll
    for (int p = 0; p < 4; p++) {
        int r = wn * 64 + p * 16 + lr;
        boff[p] = (uint32_t)(OFF_B + r * 128);
        bph[p]  = r & 7;
    }

    // cp.async fill of K-chunk t into stage base wb.
    auto issue = [&](int t, uint32_t wb) {
        uint32_t baseB = wb + OFF_B;
        const __half* gA = g_A + t * BK;
        const __half* gB = g_B + t * BK;
#pragma unroll
        for (int i = 0; i < 8; i++) {
            int idx = tid + i * THREADS;   // 0..1023
            int r = idx >> 3;              // 0..127
            int c = idx & 7;               // 0..7
            uint32_t off = sw_off(r, c);
            cp_async16(wb + off, gA + (size_t)(bM + r) * K_DIM + c * 8);
            cp_async16(baseB + off, gB + (size_t)(bN + r) * K_DIM + c * 8);
        }
    };

    // Prologue: 2 stages in flight
    issue(0, smem_base);
    CP_COMMIT();
    issue(1, smem_base + STAGE_BYTES);
    CP_COMMIT();

    uint32_t rd = smem_base;                      // stage base for tile t
    uint32_t wr = smem_base + 2 * STAGE_BYTES;    // stage base for tile t+2
    const uint32_t stage_end = smem_base + 3 * STAGE_BYTES;

    for (int t = 0; t < T_ITERS; t++) {
        CP_WAIT1();          // cp group for tile t complete
        __syncthreads();     // cross-thread visibility + stage-reuse guard

        // Preload ks=0 fragments for BOTH operands (buffer 0). The ldsm
        // latency overlaps the cp.async issue burst below.
        uint32_t bfrag[2][16];
        uint32_t afrag[2][16];
#pragma unroll
        for (int p = 0; p < 4; p++) {
            ldsm_x4(bfrag[0][p * 4 + 0], bfrag[0][p * 4 + 1],
                    bfrag[0][p * 4 + 2], bfrag[0][p * 4 + 3],
                    rd + boff[p] + (uint32_t)((lc ^ bph[p]) << 4));
        }
#pragma unroll
        for (int mt = 0; mt < 4; mt++) {
            ldsm_x4(afrag[0][mt * 4 + 0], afrag[0][mt * 4 + 1],
                    afrag[0][mt * 4 + 2], afrag[0][mt * 4 + 3],
                    rd + aoff[mt] + (uint32_t)((lc ^ aph[mt]) << 4));
        }

        if (t + 2 < T_ITERS) issue(t + 2, wr);
        CP_COMMIT();         // keep group accounting constant (may be empty)
        wr += STAGE_BYTES;
        if (wr == stage_end) wr = smem_base;

#pragma unroll
        for (int ks = 0; ks < 4; ks++) {
            const uint32_t* ac = afrag[ks & 1];
            const uint32_t* bc = bfrag[ks & 1];
            // Prefetch ALL of ks+1's fragments into the alternate buffers;
            // they complete under this ks's 32 MMAs.
            if (ks < 3) {
                uint32_t* an = afrag[(ks + 1) & 1];
                uint32_t* bn = bfrag[(ks + 1) & 1];
                int chunk = (ks + 1) * 2 + lc;
#pragma unroll
                for (int p = 0; p < 4; p++) {
                    ldsm_x4(bn[p * 4 + 0], bn[p * 4 + 1], bn[p * 4 + 2], bn[p * 4 + 3],
                            rd + boff[p] + (uint32_t)((chunk ^ bph[p]) << 4));
                }
#pragma unroll
                for (int mt = 0; mt < 4; mt++) {
                    ldsm_x4(an[mt * 4 + 0], an[mt * 4 + 1], an[mt * 4 + 2], an[mt * 4 + 3],
                            rd + aoff[mt] + (uint32_t)((chunk ^ aph[mt]) << 4));
                }
            }
#pragma unroll
            for (int mt = 0; mt < 4; mt++) {
#pragma unroll
                for (int nt = 0; nt < 8; nt++) {
                    mma_16816(acc[mt][nt], ac + mt * 4,
                              bc[(nt >> 1) * 4 + (nt & 1)],
                              bc[(nt >> 1) * 4 + (nt & 1) + 2]);
                }
            }
        }

        rd += STAGE_BYTES;
        if (rd == stage_end) rd = smem_base;
    }

    // Epilogue: fp16(acc) + fp16(bias) -> fp32 (reference semantics)
    const int g    = lane >> 2;
    const int tid4 = lane & 3;
#pragma unroll
    for (int mt = 0; mt < 4; mt++) {
#pragma unroll
        for (int nt = 0; nt < 8; nt++) {
            int row = bM + wm * 64 + mt * 16 + g;
            int col = bN + wn * 64 + nt * 8 + tid4 * 2;
            __half hb0 = __float2half_rn(bias[col]);
            __half hb1 = __float2half_rn(bias[col + 1]);
            float* c = acc[mt][nt];
            float2 v0;
            v0.x = __half2float(__hadd(__float2half_rn(c[0]), hb0));
            v0.y = __half2float(__hadd(__float2half_rn(c[1]), hb1));
            *reinterpret_cast<float2*>(out + (size_t)row * N_DIM + col) = v0;
            float2 v1;
            v1.x = __half2float(__hadd(__float2half_rn(c[2]), hb0));
            v1.y = __half2float(__hadd(__float2half_rn(c[3]), hb1));
            *reinterpret_cast<float2*>(out + (size_t)(row + 8) * N_DIM + col) = v1;
        }
    }
}

// ---------------------------------------------------------------------------
extern "C" void kernel_launch(void* const* d_in, const int* in_sizes, int n_in,
                              void* d_out, int out_size) {
    const float* x      = nullptr;   // 33554432 fp32
    const void*  wq     = nullptr;   // 45088768 (int8 OR int32-widened)
    const float* scales = nullptr;   // 352256 fp32
    const float* bias   = nullptr;   // 11008 fp32
    for (int i = 0; i < n_in; i++) {
        switch (in_sizes[i]) {
            case 33554432: x      = (const float*)d_in[i]; break;
            case 45088768: wq     = d_in[i];               break;
            case 352256:   scales = (const float*)d_in[i]; break;
            case 11008:    bias   = (const float*)d_in[i]; break;
            default: break;
        }
    }
    float* out = (float*)d_out;

    cudaFuncSetAttribute(gemm_kernel, cudaFuncAttributeMaxDynamicSharedMemorySize,
                         SMEM_TOTAL);

    detect_kernel<<<1, 256>>>((const int*)wq);
    {
        size_t nthr = (size_t)M_DIM * K_DIM / 8;
        convert_x_kernel<<<(unsigned)((nthr + 255) / 256), 256>>>(x);
    }
    {
        size_t nthr = (size_t)N_DIM * K_DIM / 8;
        dequant_w_kernel<<<(unsigned)((nthr + 255) / 256), 256>>>(wq, scales);
    }
    {
        dim3 grid(N_DIM / BN, M_DIM / BM);  // (86, 64)
        gemm_kernel<<<grid, THREADS, SMEM_TOTAL>>>(bias, out);
    }
}

// round 14
// speedup vs baseline: 1.0334x; 1.0334x over previous
#include <cuda_runtime.h>
#include <cuda_fp16.h>
#include <cstdint>

// ---------------------------------------------------------------------------
// Problem constants
// ---------------------------------------------------------------------------
#define M_DIM 8192      // 4*2048
#define N_DIM 11008
#define K_DIM 4096
#define NGROUPS 32
#define BM 128
#define BN 128
#define BK 64
#define THREADS 128     // 4 warps: 2 (M) x 2 (N), warp tile 64x64
#define T_ITERS (K_DIM / BK)   // 64
#define NSTAGES 3

// Stage: A tile 16KB + B tile 16KB (128 rows x 128B, XOR-swizzled)
#define OFF_B       16384
#define STAGE_BYTES 32768
#define SMEM_TOTAL  (NSTAGES * STAGE_BYTES)   // 96KB -> 2 CTAs/SM

// Scratch: dequantized fp16 operands (static device globals; no runtime alloc)
__device__ __half g_A[(size_t)M_DIM * K_DIM];   // x as fp16, row-major [M,K]
__device__ __half g_B[(size_t)N_DIM * K_DIM];   // W as fp16, row-major [N,K]
__device__ int g_w_wide;

static __device__ __forceinline__ uint32_t pack2(__half a, __half b) {
    __half2 h = __halves2half2(a, b);
    return *reinterpret_cast<uint32_t*>(&h);
}

// ---------------------------------------------------------------------------
// Pre-pass kernels (unchanged)
// ---------------------------------------------------------------------------
__global__ void detect_kernel(const int* __restrict__ w) {
    __shared__ int any_big;
    if (threadIdx.x == 0) any_big = 0;
    __syncthreads();
    int big = 0;
    for (int i = threadIdx.x; i < 4096; i += blockDim.x) {
        int v = w[i];
        if (v > 127 || v < -128) big = 1;
    }
    if (big) any_big = 1;
    __syncthreads();
    if (threadIdx.x == 0) g_w_wide = any_big ? 0 : 1;
}

__global__ void convert_x_kernel(const float* __restrict__ x) {
    size_t i = (size_t)blockIdx.x * blockDim.x + threadIdx.x;
    if (i >= (size_t)M_DIM * K_DIM / 8) return;
    const float4* p = reinterpret_cast<const float4*>(x) + i * 2;
    float4 u = p[0];
    float4 v = p[1];
    uint4 o;
    o.x = pack2(__float2half_rn(u.x), __float2half_rn(u.y));
    o.y = pack2(__float2half_rn(u.z), __float2half_rn(u.w));
    o.z = pack2(__float2half_rn(v.x), __float2half_rn(v.y));
    o.w = pack2(__float2half_rn(v.z), __float2half_rn(v.w));
    reinterpret_cast<uint4*>(g_A)[i] = o;
}

__global__ void dequant_w_kernel(const void* __restrict__ wq,
                                 const float* __restrict__ scales) {
    size_t i = (size_t)blockIdx.x * blockDim.x + threadIdx.x;
    if (i >= (size_t)N_DIM * K_DIM / 8) return;
    size_t kc = i % (K_DIM / 8);
    size_t n  = i / (K_DIM / 8);
    float s = scales[n * NGROUPS + (kc >> 4)];
    int q[8];
    if (g_w_wide) {
        const int4* p = reinterpret_cast<const int4*>(wq) + i * 2;
        int4 a = p[0];
        int4 b = p[1];
        q[0] = a.x; q[1] = a.y; q[2] = a.z; q[3] = a.w;
        q[4] = b.x; q[5] = b.y; q[6] = b.z; q[7] = b.w;
    } else {
        int2 w = reinterpret_cast<const int2*>(wq)[i];
#pragma unroll
        for (int b = 0; b < 4; b++) {
            q[b]     = (int)(int8_t)(w.x >> (8 * b));
            q[b + 4] = (int)(int8_t)(w.y >> (8 * b));
        }
    }
    __half h[8];
#pragma unroll
    for (int j = 0; j < 8; j++) h[j] = __float2half_rn((float)q[j] * s);
    uint4 o;
    o.x = pack2(h[0], h[1]);
    o.y = pack2(h[2], h[3]);
    o.z = pack2(h[4], h[5]);
    o.w = pack2(h[6], h[7]);
    reinterpret_cast<uint4*>(g_B)[i] = o;
}

// ---------------------------------------------------------------------------
// GEMM: C = A * B^T, fp16 mma.sync, fp32 acc; epilogue fp16(acc)+fp16(bias).
// 128x128x64 tile, 128 threads (4 warps, 2x2), warp tile 64x64, 2 CTAs/SM.
// B fragments double-buffered across ks steps; A fragments ping-pong buffered
// at mt granularity (+4 regs only): every ldsm gets a full MMA-window to land.
// ---------------------------------------------------------------------------
__device__ __forceinline__ void cp_async16(uint32_t dst, const void* src) {
    asm volatile("cp.async.cg.shared.global [%0], [%1], 16;\n" ::"r"(dst), "l"(src));
}
#define CP_COMMIT() asm volatile("cp.async.commit_group;\n")
#define CP_WAIT1()  asm volatile("cp.async.wait_group 1;\n")

__device__ __forceinline__ void ldsm_x4(uint32_t& r0, uint32_t& r1, uint32_t& r2,
                                        uint32_t& r3, uint32_t addr) {
    asm volatile("ldmatrix.sync.aligned.m8n8.x4.shared.b16 {%0,%1,%2,%3}, [%4];\n"
                 : "=r"(r0), "=r"(r1), "=r"(r2), "=r"(r3)
                 : "r"(addr));
}
__device__ __forceinline__ void mma_16816(float* c, const uint32_t* a,
                                          uint32_t b0, uint32_t b1) {
    asm volatile(
        "mma.sync.aligned.m16n8k16.row.col.f32.f16.f16.f32 "
        "{%0,%1,%2,%3},{%4,%5,%6,%7},{%8,%9},{%0,%1,%2,%3};\n"
        : "+f"(c[0]), "+f"(c[1]), "+f"(c[2]), "+f"(c[3])
        : "r"(a[0]), "r"(a[1]), "r"(a[2]), "r"(a[3]), "r"(b0), "r"(b1));
}

// Swizzled smem byte offset: row r (128B rows), 16B-chunk c
__device__ __forceinline__ uint32_t sw_off(int r, int c) {
    return (uint32_t)(r * 128 + ((c ^ (r & 7)) << 4));
}

__global__ void __launch_bounds__(THREADS, 2)
gemm_kernel(const float* __restrict__ bias, float* __restrict__ out) {
    extern __shared__ char smem[];
    const int tid  = threadIdx.x;
    const int lane = tid & 31;
    const int warp = tid >> 5;
    const int wm = warp >> 1;       // 0..1 (M: 64 rows each)
    const int wn = warp & 1;        // 0..1 (N: 64 cols each)
    const int bM = blockIdx.y * BM;
    const int bN = blockIdx.x * BN;

    const uint32_t smem_base = (uint32_t)__cvta_generic_to_shared(smem);

    float acc[4][8][4];
#pragma unroll
    for (int i = 0; i < 4; i++)
#pragma unroll
        for (int j = 0; j < 8; j++)
#pragma unroll
            for (int k = 0; k < 4; k++) acc[i][j][k] = 0.f;

    // Precompute fragment-row smem offsets and swizzle phases (loop-invariant)
    const int lr = lane & 15;
    const int lc = lane >> 4;
    uint32_t aoff[4], boff[4];
    int aph[4], bph[4];
#pragma unroll
    for (int mt = 0; mt < 4; mt++) {
        int r = wm * 64 + mt * 16 + lr;
        aoff[mt] = (uint32_t)(r * 128);
        aph[mt]  = r & 7;
    }
#pragma unroll
    for (int p = 0; p < 4; p++) {
        int r = wn * 64 + p * 16 + lr;
        boff[p] = (uint32_t)(OFF_B + r * 128);
        bph[p]  = r & 7;
    }

    // cp.async fill of K-chunk t into stage base wb.
    auto issue = [&](int t, uint32_t wb) {
        uint32_t baseB = wb + OFF_B;
        const __half* gA = g_A + t * BK;
        const __half* gB = g_B + t * BK;
#pragma unroll
        for (int i = 0; i < 8; i++) {
            int idx = tid + i * THREADS;   // 0..1023
            int r = idx >> 3;              // 0..127
            int c = idx & 7;               // 0..7
            uint32_t off = sw_off(r, c);
            cp_async16(wb + off, gA + (size_t)(bM + r) * K_DIM + c * 8);
            cp_async16(baseB + off, gB + (size_t)(bN + r) * K_DIM + c * 8);
        }
    };

    // Prologue: 2 stages in flight
    issue(0, smem_base);
    CP_COMMIT();
    issue(1, smem_base + STAGE_BYTES);
    CP_COMMIT();

    uint32_t rd = smem_base;                      // stage base for tile t
    uint32_t wr = smem_base + 2 * STAGE_BYTES;    // stage base for tile t+2
    const uint32_t stage_end = smem_base + 3 * STAGE_BYTES;

    for (int t = 0; t < T_ITERS; t++) {
        CP_WAIT1();          // cp group for tile t complete
        __syncthreads();     // cross-thread visibility + stage-reuse guard

        // Preload ks=0 B fragments (buffer 0) and the first A fragment
        // (ks=0, mt=0) into A buffer 0; latency overlaps the cp.async burst.
        uint32_t bfrag[2][16];
        uint32_t abuf[2][4];
#pragma unroll
        for (int p = 0; p < 4; p++) {
            ldsm_x4(bfrag[0][p * 4 + 0], bfrag[0][p * 4 + 1],
                    bfrag[0][p * 4 + 2], bfrag[0][p * 4 + 3],
                    rd + boff[p] + (uint32_t)((lc ^ bph[p]) << 4));
        }
        ldsm_x4(abuf[0][0], abuf[0][1], abuf[0][2], abuf[0][3],
                rd + aoff[0] + (uint32_t)((lc ^ aph[0]) << 4));

        if (t + 2 < T_ITERS) issue(t + 2, wr);
        CP_COMMIT();         // keep group accounting constant (may be empty)
        wr += STAGE_BYTES;
        if (wr == stage_end) wr = smem_base;

#pragma unroll
        for (int ks = 0; ks < 4; ks++) {
            const uint32_t* bc = bfrag[ks & 1];
            // Prefetch next ks's B fragments (4 ldsm) under this ks's MMAs.
            if (ks < 3) {
                uint32_t* bn = bfrag[(ks + 1) & 1];
                int chunk = (ks + 1) * 2 + lc;
#pragma unroll
                for (int p = 0; p < 4; p++) {
                    ldsm_x4(bn[p * 4 + 0], bn[p * 4 + 1], bn[p * 4 + 2], bn[p * 4 + 3],
                            rd + boff[p] + (uint32_t)((chunk ^ bph[p]) << 4));
                }
            }
            int chunk = ks * 2 + lc;
#pragma unroll
            for (int mt = 0; mt < 4; mt++) {
                // Prefetch the NEXT A fragment into the alternate buffer:
                // (ks, mt+1), or (ks+1, 0) at the ks boundary.
                if (mt < 3) {
                    uint32_t* an = abuf[(mt + 1) & 1];
                    ldsm_x4(an[0], an[1], an[2], an[3],
                            rd + aoff[mt + 1] + (uint32_t)((chunk ^ aph[mt + 1]) << 4));
                } else if (ks < 3) {
                    uint32_t* an = abuf[0];
                    int nchunk = (ks + 1) * 2 + lc;
                    ldsm_x4(an[0], an[1], an[2], an[3],
                            rd + aoff[0] + (uint32_t)((nchunk ^ aph[0]) << 4));
                }
                const uint32_t* a = abuf[mt & 1];
#pragma unroll
                for (int nt = 0; nt < 8; nt++) {
                    mma_16816(acc[mt][nt], a,
                              bc[(nt >> 1) * 4 + (nt & 1)],
                              bc[(nt >> 1) * 4 + (nt & 1) + 2]);
                }
            }
        }

        rd += STAGE_BYTES;
        if (rd == stage_end) rd = smem_base;
    }

    // Epilogue: fp16(acc) + fp16(bias) -> fp32 (reference semantics)
    const int g    = lane >> 2;
    const int tid4 = lane & 3;
#pragma unroll
    for (int mt = 0; mt < 4; mt++) {
#pragma unroll
        for (int nt = 0; nt < 8; nt++) {
            int row = bM + wm * 64 + mt * 16 + g;
            int col = bN + wn * 64 + nt * 8 + tid4 * 2;
            __half hb0 = __float2half_rn(bias[col]);
            __half hb1 = __float2half_rn(bias[col + 1]);
            float* c = acc[mt][nt];
            float2 v0;
            v0.x = __half2float(__hadd(__float2half_rn(c[0]), hb0));
            v0.y = __half2float(__hadd(__float2half_rn(c[1]), hb1));
            *reinterpret_cast<float2*>(out + (size_t)row * N_DIM + col) = v0;
            float2 v1;
            v1.x = __half2float(__hadd(__float2half_rn(c[2]), hb0));
            v1.y = __half2float(__hadd(__float2half_rn(c[3]), hb1));
            *reinterpret_cast<float2*>(out + (size_t)(row + 8) * N_DIM + col) = v1;
        }
    }
}

// ---------------------------------------------------------------------------
extern "C" void kernel_launch(void* const* d_in, const int* in_sizes, int n_in,
                              void* d_out, int out_size) {
    const float* x      = nullptr;   // 33554432 fp32
    const void*  wq     = nullptr;   // 45088768 (int8 OR int32-widened)
    const float* scales = nullptr;   // 352256 fp32
    const float* bias   = nullptr;   // 11008 fp32
    for (int i = 0; i < n_in; i++) {
        switch (in_sizes[i]) {
            case 33554432: x      = (const float*)d_in[i]; break;
            case 45088768: wq     = d_in[i];               break;
            case 352256:   scales = (const float*)d_in[i]; break;
            case 11008:    bias   = (const float*)d_in[i]; break;
            default: break;
        }
    }
    float* out = (float*)d_out;

    cudaFuncSetAttribute(gemm_kernel, cudaFuncAttributeMaxDynamicSharedMemorySize,
                         SMEM_TOTAL);

    detect_kernel<<<1, 256>>>((const int*)wq);
    {
        size_t nthr = (size_t)M_DIM * K_DIM / 8;
        convert_x_kernel<<<(unsigned)((nthr + 255) / 256), 256>>>(x);
    }
    {
        size_t nthr = (size_t)N_DIM * K_DIM / 8;
        dequant_w_kernel<<<(unsigned)((nthr + 255) / 256), 256>>>(wq, scales);
    }
    {
        dim3 grid(N_DIM / BN, M_DIM / BM);  // (86, 64)
        gemm_kernel<<<grid, THREADS, SMEM_TOTAL>>>(bias, out);
    }
}

// round 15
// speedup vs baseline: 1.0772x; 1.0424x over previous
#include <cuda_runtime.h>
#include <cuda_fp16.h>
#include <cstdint>

// ---------------------------------------------------------------------------
// Problem constants
// ---------------------------------------------------------------------------
#define M_DIM 8192      // 4*2048
#define N_DIM 11008
#define K_DIM 4096
#define NGROUPS 32
#define BM 128
#define BN 128
#define BK 64
#define THREADS 128     // 4 warps: 2 (M) x 2 (N), warp tile 64x64
#define T_ITERS (K_DIM / BK)   // 64
#define NSTAGES 3
#define ROWSTRIDE16 (16 * K_DIM)   // halves between a thread's cp chunks

// Stage: A tile 16KB + B tile 16KB (128 rows x 128B, XOR-swizzled)
#define OFF_B       16384
#define STAGE_BYTES 32768
#define SMEM_TOTAL  (NSTAGES * STAGE_BYTES)   // 96KB -> 2 CTAs/SM

// Scratch: dequantized fp16 operands (static device globals; no runtime alloc)
__device__ __half g_A[(size_t)M_DIM * K_DIM];   // x as fp16, row-major [M,K]
__device__ __half g_B[(size_t)N_DIM * K_DIM];   // W as fp16, row-major [N,K]
__device__ int g_w_wide;

static __device__ __forceinline__ uint32_t pack2(__half a, __half b) {
    __half2 h = __halves2half2(a, b);
    return *reinterpret_cast<uint32_t*>(&h);
}

// ---------------------------------------------------------------------------
// Pre-pass kernels (unchanged)
// ---------------------------------------------------------------------------
__global__ void detect_kernel(const int* __restrict__ w) {
    __shared__ int any_big;
    if (threadIdx.x == 0) any_big = 0;
    __syncthreads();
    int big = 0;
    for (int i = threadIdx.x; i < 4096; i += blockDim.x) {
        int v = w[i];
        if (v > 127 || v < -128) big = 1;
    }
    if (big) any_big = 1;
    __syncthreads();
    if (threadIdx.x == 0) g_w_wide = any_big ? 0 : 1;
}

__global__ void convert_x_kernel(const float* __restrict__ x) {
    size_t i = (size_t)blockIdx.x * blockDim.x + threadIdx.x;
    if (i >= (size_t)M_DIM * K_DIM / 8) return;
    const float4* p = reinterpret_cast<const float4*>(x) + i * 2;
    float4 u = p[0];
    float4 v = p[1];
    uint4 o;
    o.x = pack2(__float2half_rn(u.x), __float2half_rn(u.y));
    o.y = pack2(__float2half_rn(u.z), __float2half_rn(u.w));
    o.z = pack2(__float2half_rn(v.x), __float2half_rn(v.y));
    o.w = pack2(__float2half_rn(v.z), __float2half_rn(v.w));
    reinterpret_cast<uint4*>(g_A)[i] = o;
}

__global__ void dequant_w_kernel(const void* __restrict__ wq,
                                 const float* __restrict__ scales) {
    size_t i = (size_t)blockIdx.x * blockDim.x + threadIdx.x;
    if (i >= (size_t)N_DIM * K_DIM / 8) return;
    size_t kc = i % (K_DIM / 8);
    size_t n  = i / (K_DIM / 8);
    float s = scales[n * NGROUPS + (kc >> 4)];
    int q[8];
    if (g_w_wide) {
        const int4* p = reinterpret_cast<const int4*>(wq) + i * 2;
        int4 a = p[0];
        int4 b = p[1];
        q[0] = a.x; q[1] = a.y; q[2] = a.z; q[3] = a.w;
        q[4] = b.x; q[5] = b.y; q[6] = b.z; q[7] = b.w;
    } else {
        int2 w = reinterpret_cast<const int2*>(wq)[i];
#pragma unroll
        for (int b = 0; b < 4; b++) {
            q[b]     = (int)(int8_t)(w.x >> (8 * b));
            q[b + 4] = (int)(int8_t)(w.y >> (8 * b));
        }
    }
    __half h[8];
#pragma unroll
    for (int j = 0; j < 8; j++) h[j] = __float2half_rn((float)q[j] * s);
    uint4 o;
    o.x = pack2(h[0], h[1]);
    o.y = pack2(h[2], h[3]);
    o.z = pack2(h[4], h[5]);
    o.w = pack2(h[6], h[7]);
    reinterpret_cast<uint4*>(g_B)[i] = o;
}

// ---------------------------------------------------------------------------
// GEMM: C = A * B^T, fp16 mma.sync, fp32 acc; epilogue fp16(acc)+fp16(bias).
// 128x128x64 tile, 128 threads (4 warps, 2x2), warp tile 64x64, 2 CTAs/SM.
// B double-buffered per ks; A ping-pong per mt. NEW: cp.async addressing
// strength-reduced to one running pointer + one smem offset per thread, and
// the 16 copies are spread across the 4 ks steps (issue under MMA cover).
// ---------------------------------------------------------------------------
__device__ __forceinline__ void cp_async16(uint32_t dst, const void* src) {
    asm volatile("cp.async.cg.shared.global [%0], [%1], 16;\n" ::"r"(dst), "l"(src));
}
#define CP_COMMIT() asm volatile("cp.async.commit_group;\n")
#define CP_WAIT1()  asm volatile("cp.async.wait_group 1;\n")

__device__ __forceinline__ void ldsm_x4(uint32_t& r0, uint32_t& r1, uint32_t& r2,
                                        uint32_t& r3, uint32_t addr) {
    asm volatile("ldmatrix.sync.aligned.m8n8.x4.shared.b16 {%0,%1,%2,%3}, [%4];\n"
                 : "=r"(r0), "=r"(r1), "=r"(r2), "=r"(r3)
                 : "r"(addr));
}
__device__ __forceinline__ void mma_16816(float* c, const uint32_t* a,
                                          uint32_t b0, uint32_t b1) {
    asm volatile(
        "mma.sync.aligned.m16n8k16.row.col.f32.f16.f16.f32 "
        "{%0,%1,%2,%3},{%4,%5,%6,%7},{%8,%9},{%0,%1,%2,%3};\n"
        : "+f"(c[0]), "+f"(c[1]), "+f"(c[2]), "+f"(c[3])
        : "r"(a[0]), "r"(a[1]), "r"(a[2]), "r"(a[3]), "r"(b0), "r"(b1));
}

__global__ void __launch_bounds__(THREADS, 2)
gemm_kernel(const float* __restrict__ bias, float* __restrict__ out) {
    extern __shared__ char smem[];
    const int tid  = threadIdx.x;
    const int lane = tid & 31;
    const int warp = tid >> 5;
    const int wm = warp >> 1;       // 0..1 (M: 64 rows each)
    const int wn = warp & 1;        // 0..1 (N: 64 cols each)
    const int bM = blockIdx.y * BM;
    const int bN = blockIdx.x * BN;

    const uint32_t smem_base = (uint32_t)__cvta_generic_to_shared(smem);

    float acc[4][8][4];
#pragma unroll
    for (int i = 0; i < 4; i++)
#pragma unroll
        for (int j = 0; j < 8; j++)
#pragma unroll
            for (int k = 0; k < 4; k++) acc[i][j][k] = 0.f;

    // Fragment-row smem offsets / swizzle phases (loop-invariant)
    const int lr = lane & 15;
    const int lc = lane >> 4;
    uint32_t aoff[4], boff[4];
    int aph[4], bph[4];
#pragma unroll
    for (int mt = 0; mt < 4; mt++) {
        int r = wm * 64 + mt * 16 + lr;
        aoff[mt] = (uint32_t)(r * 128);
        aph[mt]  = r & 7;
    }
#pragma unroll
    for (int p = 0; p < 4; p++) {
        int r = wn * 64 + p * 16 + lr;
        boff[p] = (uint32_t)(OFF_B + r * 128);
        bph[p]  = r & 7;
    }

    // cp.async strength reduction: thread owns chunks (r0+16i, c0), i=0..7.
    // Swizzle phase depends only on r0&7 (16i doesn't change it), so
    // smem offset = soff + i*2048; gmem ptr advances 16*K_DIM per i, BK per t.
    const int r0 = tid >> 3;
    const int c0 = tid & 7;
    const uint32_t soff = (uint32_t)(r0 * 128 + ((c0 ^ (r0 & 7)) << 4));
    const __half* pA0 = g_A + (size_t)(bM + r0) * K_DIM + c0 * 8;
    const __half* pB0 = g_B + (size_t)(bN + r0) * K_DIM + c0 * 8;

    // Prologue: fill stages 0 and 1 (tiles 0 and 1)
#pragma unroll
    for (int s = 0; s < 2; s++) {
        uint32_t wbA = smem_base + s * STAGE_BYTES + soff;
        uint32_t wbB = wbA + OFF_B;
        const __half* sA = pA0 + s * BK;
        const __half* sB = pB0 + s * BK;
#pragma unroll
        for (int i = 0; i < 8; i++) {
            cp_async16(wbA + i * 2048, sA + (size_t)i * ROWSTRIDE16);
            cp_async16(wbB + i * 2048, sB + (size_t)i * ROWSTRIDE16);
        }
        CP_COMMIT();
    }

    const __half* pAn = pA0 + 2 * BK;   // gmem source for tile t+2
    const __half* pBn = pB0 + 2 * BK;

    uint32_t rd = smem_base;                      // stage base for tile t
    uint32_t wr = smem_base + 2 * STAGE_BYTES;    // stage base for tile t+2
    const uint32_t stage_end = smem_base + 3 * STAGE_BYTES;

    for (int t = 0; t < T_ITERS; t++) {
        CP_WAIT1();          // cp group for tile t complete
        __syncthreads();     // cross-thread visibility + stage-reuse guard

        // Preload ks=0 B fragments (buffer 0) and A(ks=0, mt=0).
        uint32_t bfrag[2][16];
        uint32_t abuf[2][4];
#pragma unroll
        for (int p = 0; p < 4; p++) {
            ldsm_x4(bfrag[0][p * 4 + 0], bfrag[0][p * 4 + 1],
                    bfrag[0][p * 4 + 2], bfrag[0][p * 4 + 3],
                    rd + boff[p] + (uint32_t)((lc ^ bph[p]) << 4));
        }
        ldsm_x4(abuf[0][0], abuf[0][1], abuf[0][2], abuf[0][3],
                rd + aoff[0] + (uint32_t)((lc ^ aph[0]) << 4));

        const bool do_cp = (t + 2 < T_ITERS);
        const uint32_t wbA = wr + soff;
        const uint32_t wbB = wbA + OFF_B;

#pragma unroll
        for (int ks = 0; ks < 4; ks++) {
            const uint32_t* bc = bfrag[ks & 1];
            // Prefetch next ks's B fragments under this ks's MMAs.
            if (ks < 3) {
                uint32_t* bn = bfrag[(ks + 1) & 1];
                int chunk = (ks + 1) * 2 + lc;
#pragma unroll
                for (int p = 0; p < 4; p++) {
                    ldsm_x4(bn[p * 4 + 0], bn[p * 4 + 1], bn[p * 4 + 2], bn[p * 4 + 3],
                            rd + boff[p] + (uint32_t)((chunk ^ bph[p]) << 4));
                }
            }
            // Spread tile-(t+2) copies: 2 A + 2 B chunks per ks.
            if (do_cp) {
#pragma unroll
                for (int j = 0; j < 2; j++) {
                    int i = ks * 2 + j;
                    cp_async16(wbA + i * 2048, pAn + (size_t)i * ROWSTRIDE16);
                    cp_async16(wbB + i * 2048, pBn + (size_t)i * ROWSTRIDE16);
                }
            }
            int chunk = ks * 2 + lc;
#pragma unroll
            for (int mt = 0; mt < 4; mt++) {
                // A ping-pong: prefetch (ks, mt+1) or (ks+1, 0).
                if (mt < 3) {
                    uint32_t* an = abuf[(mt + 1) & 1];
                    ldsm_x4(an[0], an[1], an[2], an[3],
                            rd + aoff[mt + 1] + (uint32_t)((chunk ^ aph[mt + 1]) << 4));
                } else if (ks < 3) {
                    uint32_t* an = abuf[0];
                    int nchunk = (ks + 1) * 2 + lc;
                    ldsm_x4(an[0], an[1], an[2], an[3],
                            rd + aoff[0] + (uint32_t)((nchunk ^ aph[0]) << 4));
                }
                const uint32_t* a = abuf[mt & 1];
#pragma unroll
                for (int nt = 0; nt < 8; nt++) {
                    mma_16816(acc[mt][nt], a,
                              bc[(nt >> 1) * 4 + (nt & 1)],
                              bc[(nt >> 1) * 4 + (nt & 1) + 2]);
                }
            }
        }
        CP_COMMIT();         // close tile-(t+2)'s group (may be empty)

        pAn += BK;
        pBn += BK;
        rd += STAGE_BYTES;
        if (rd == stage_end) rd = smem_base;
        wr += STAGE_BYTES;
        if (wr == stage_end) wr = smem_base;
    }

    // Epilogue: fp16(acc) + fp16(bias) -> fp32 (reference semantics)
    const int g    = lane >> 2;
    const int tid4 = lane & 3;
#pragma unroll
    for (int mt = 0; mt < 4; mt++) {
#pragma unroll
        for (int nt = 0; nt < 8; nt++) {
            int row = bM + wm * 64 + mt * 16 + g;
            int col = bN + wn * 64 + nt * 8 + tid4 * 2;
            __half hb0 = __float2half_rn(bias[col]);
            __half hb1 = __float2half_rn(bias[col + 1]);
            float* c = acc[mt][nt];
            float2 v0;
            v0.x = __half2float(__hadd(__float2half_rn(c[0]), hb0));
            v0.y = __half2float(__hadd(__float2half_rn(c[1]), hb1));
            *reinterpret_cast<float2*>(out + (size_t)row * N_DIM + col) = v0;
            float2 v1;
            v1.x = __half2float(__hadd(__float2half_rn(c[2]), hb0));
            v1.y = __half2float(__hadd(__float2half_rn(c[3]), hb1));
            *reinterpret_cast<float2*>(out + (size_t)(row + 8) * N_DIM + col) = v1;
        }
    }
}

// ---------------------------------------------------------------------------
extern "C" void kernel_launch(void* const* d_in, const int* in_sizes, int n_in,
                              void* d_out, int out_size) {
    const float* x      = nullptr;   // 33554432 fp32
    const void*  wq     = nullptr;   // 45088768 (int8 OR int32-widened)
    const float* scales = nullptr;   // 352256 fp32
    const float* bias   = nullptr;   // 11008 fp32
    for (int i = 0; i < n_in; i++) {
        switch (in_sizes[i]) {
            case 33554432: x      = (const float*)d_in[i]; break;
            case 45088768: wq     = d_in[i];               break;
            case 352256:   scales = (const float*)d_in[i]; break;
            case 11008:    bias   = (const float*)d_in[i]; break;
            default: break;
        }
    }
    float* out = (float*)d_out;

    cudaFuncSetAttribute(gemm_kernel, cudaFuncAttributeMaxDynamicSharedMemorySize,
                         SMEM_TOTAL);

    detect_kernel<<<1, 256>>>((const int*)wq);
    {
        size_t nthr = (size_t)M_DIM * K_DIM / 8;
        convert_x_kernel<<<(unsigned)((nthr + 255) / 256), 256>>>(x);
    }
    {
        size_t nthr = (size_t)N_DIM * K_DIM / 8;
        dequant_w_kernel<<<(unsigned)((nthr + 255) / 256), 256>>>(wq, scales);
    }
    {
        dim3 grid(N_DIM / BN, M_DIM / BM);  // (86, 64)
        gemm_kernel<<<grid, THREADS, SMEM_TOTAL>>>(bias, out);
    }
}

// round 16
// speedup vs baseline: 1.0975x; 1.0189x over previous
#include <cuda_runtime.h>
#include <cuda_fp16.h>
#include <cstdint>

// ---------------------------------------------------------------------------
// Problem constants
// ---------------------------------------------------------------------------
#define M_DIM 8192      // 4*2048
#define N_DIM 11008
#define K_DIM 4096
#define NGROUPS 32
#define BM 128
#define BN 128
#define BK 64
#define THREADS 128     // 4 warps: 2 (M) x 2 (N), warp tile 64x64
#define T_ITERS (K_DIM / BK)   // 64
#define NSTAGES 3
#define TILE_BYTES 16384       // one operand tile: 128 rows x 128B (swizzled)

// Stage: A tile 16KB + B tile 16KB
#define OFF_B       16384
#define STAGE_BYTES 32768
#define SMEM_MBAR   (NSTAGES * STAGE_BYTES)     // 98304
#define SMEM_TOTAL  (SMEM_MBAR + 64)            // mbarriers: full[3], empty[3]

// Scratch, TILED + PRE-SWIZZLED layout:
//  g_A: block (mTile*T_ITERS + t) is a contiguous 16KB swizzled tile
//  g_B: block (nTile*T_ITERS + t) likewise
__device__ __half g_A[(size_t)M_DIM * K_DIM];
__device__ __half g_B[(size_t)N_DIM * K_DIM];
__device__ int g_w_wide;

static __device__ __forceinline__ uint32_t pack2(__half a, __half b) {
    __half2 h = __halves2half2(a, b);
    return *reinterpret_cast<uint32_t*>(&h);
}

// ---------------------------------------------------------------------------
// Pre-pass kernels — now write tiled, swizzled blocks
// ---------------------------------------------------------------------------
__global__ void detect_kernel(const int* __restrict__ w) {
    __shared__ int any_big;
    if (threadIdx.x == 0) any_big = 0;
    __syncthreads();
    int big = 0;
    for (int i = threadIdx.x; i < 4096; i += blockDim.x) {
        int v = w[i];
        if (v > 127 || v < -128) big = 1;
    }
    if (big) any_big = 1;
    __syncthreads();
    if (threadIdx.x == 0) g_w_wide = any_big ? 0 : 1;
}

// 8 halves (one 16B swizzle chunk) per thread.
__global__ void convert_x_kernel(const float* __restrict__ x) {
    size_t i = (size_t)blockIdx.x * blockDim.x + threadIdx.x;
    if (i >= (size_t)M_DIM * K_DIM / 8) return;
    int kc = (int)(i & 511);          // K/8 = 512 chunks per row
    size_t m = i >> 9;
    int t = kc >> 3;                  // K-tile (64 halves = 8 chunks)
    int c = kc & 7;
    int r = (int)(m & 127);
    size_t mb = m >> 7;
    const float4* p = reinterpret_cast<const float4*>(x + m * K_DIM + (size_t)kc * 8);
    float4 u = p[0];
    float4 v = p[1];
    uint4 o;
    o.x = pack2(__float2half_rn(u.x), __float2half_rn(u.y));
    o.y = pack2(__float2half_rn(u.z), __float2half_rn(u.w));
    o.z = pack2(__float2half_rn(v.x), __float2half_rn(v.y));
    o.w = pack2(__float2half_rn(v.z), __float2half_rn(v.w));
    size_t dst = ((mb * T_ITERS + t) << 14) + (size_t)(r * 128 + (((c ^ (r & 7)) << 4)));
    *reinterpret_cast<uint4*>(reinterpret_cast<char*>(g_A) + dst) = o;
}

__global__ void dequant_w_kernel(const void* __restrict__ wq,
                                 const float* __restrict__ scales) {
    size_t i = (size_t)blockIdx.x * blockDim.x + threadIdx.x;
    if (i >= (size_t)N_DIM * K_DIM / 8) return;
    int kc = (int)(i & 511);
    size_t n = i >> 9;
    float s = scales[n * NGROUPS + (kc >> 4)];
    int q[8];
    if (g_w_wide) {
        const int4* p = reinterpret_cast<const int4*>(wq) + i * 2;
        int4 a = p[0];
        int4 b = p[1];
        q[0] = a.x; q[1] = a.y; q[2] = a.z; q[3] = a.w;
        q[4] = b.x; q[5] = b.y; q[6] = b.z; q[7] = b.w;
    } else {
        int2 w = reinterpret_cast<const int2*>(wq)[i];
#pragma unroll
        for (int b = 0; b < 4; b++) {
            q[b]     = (int)(int8_t)(w.x >> (8 * b));
            q[b + 4] = (int)(int8_t)(w.y >> (8 * b));
        }
    }
    __half h[8];
#pragma unroll
    for (int j = 0; j < 8; j++) h[j] = __float2half_rn((float)q[j] * s);
    uint4 o;
    o.x = pack2(h[0], h[1]);
    o.y = pack2(h[2], h[3]);
    o.z = pack2(h[4], h[5]);
    o.w = pack2(h[6], h[7]);
    int t = kc >> 3;
    int c = kc & 7;
    int r = (int)(n & 127);
    size_t nb = n >> 7;
    size_t dst = ((nb * T_ITERS + t) << 14) + (size_t)(r * 128 + (((c ^ (r & 7)) << 4)));
    *reinterpret_cast<uint4*>(reinterpret_cast<char*>(g_B) + dst) = o;
}

// ---------------------------------------------------------------------------
// mbarrier + bulk-copy helpers
// ---------------------------------------------------------------------------
#define MBAR_INIT(mbar, cnt) \
    asm volatile("mbarrier.init.shared.b64 [%0], %1;" \
                 :: "r"((uint32_t)(mbar)), "r"((uint32_t)(cnt)) : "memory")
#define MBAR_EXPECT_TX(mbar, bytes) \
    asm volatile("mbarrier.arrive.expect_tx.shared.b64 _, [%0], %1;" \
                 :: "r"((uint32_t)(mbar)), "r"((uint32_t)(bytes)) : "memory")
#define MBAR_ARRIVE(mbar) \
    asm volatile("mbarrier.arrive.shared.b64 _, [%0];" \
                 :: "r"((uint32_t)(mbar)) : "memory")
#define MBAR_WAIT(mbar, parity) do {                                              \
    uint32_t _m = (uint32_t)(mbar);                                               \
    uint32_t _p = (uint32_t)(parity);                                             \
    uint32_t _done;                                                               \
    asm volatile("{\n\t.reg .pred p;\n\t"                                         \
        "mbarrier.try_wait.parity.acquire.cta.shared::cta.b64 p, [%1], %2;\n\t"   \
        "selp.b32 %0, 1, 0, p;\n\t}" : "=r"(_done) : "r"(_m), "r"(_p) : "memory"); \
    if (!_done) {                                                                 \
        asm volatile("{\n\t.reg .pred P1;\n\t"                                    \
            "WL_%=:\n\t"                                                          \
            "mbarrier.try_wait.parity.acquire.cta.shared::cta.b64 P1, [%0], %1, 0x989680;\n\t" \
            "@P1 bra.uni WD_%=;\n\t"                                              \
            "bra.uni WL_%=;\n\t"                                                  \
            "WD_%=:\n\t}" :: "r"(_m), "r"(_p) : "memory");                        \
    }                                                                             \
} while (0)
#define BULK_G2S(dst, src, bytes, mbar) \
    asm volatile("cp.async.bulk.shared::cluster.global.mbarrier::complete_tx::bytes " \
                 "[%0], [%1], %2, [%3];" \
                 :: "r"((uint32_t)(dst)), "l"(src), "r"((uint32_t)(bytes)), \
                    "r"((uint32_t)(mbar)) : "memory")

__device__ __forceinline__ void ldsm_x4(uint32_t& r0, uint32_t& r1, uint32_t& r2,
                                        uint32_t& r3, uint32_t addr) {
    asm volatile("ldmatrix.sync.aligned.m8n8.x4.shared.b16 {%0,%1,%2,%3}, [%4];\n"
                 : "=r"(r0), "=r"(r1), "=r"(r2), "=r"(r3)
                 : "r"(addr));
}
__device__ __forceinline__ void mma_16816(float* c, const uint32_t* a,
                                          uint32_t b0, uint32_t b1) {
    asm volatile(
        "mma.sync.aligned.m16n8k16.row.col.f32.f16.f16.f32 "
        "{%0,%1,%2,%3},{%4,%5,%6,%7},{%8,%9},{%0,%1,%2,%3};\n"
        : "+f"(c[0]), "+f"(c[1]), "+f"(c[2]), "+f"(c[3])
        : "r"(a[0]), "r"(a[1]), "r"(a[2]), "r"(a[3]), "r"(b0), "r"(b1));
}

// ---------------------------------------------------------------------------
// GEMM: mbarrier-piped. No __syncthreads / no per-thread copies in mainloop.
// Producer (tid 0): waits stage-empty, expect_tx(32KB), 2x cp.async.bulk.
// Consumers: wait stage-full (acquire), pure ldsm+mma, 1 arrive/warp on empty.
// ---------------------------------------------------------------------------
__global__ void __launch_bounds__(THREADS, 2)
gemm_kernel(const float* __restrict__ bias, float* __restrict__ out) {
    extern __shared__ char smem[];
    const int tid  = threadIdx.x;
    const int lane = tid & 31;
    const int warp = tid >> 5;
    const int wm = warp >> 1;
    const int wn = warp & 1;
    const int bM = blockIdx.y * BM;
    const int bN = blockIdx.x * BN;

    const uint32_t sbase = (uint32_t)__cvta_generic_to_shared(smem);
    const uint32_t fullb  = sbase + SMEM_MBAR;        // full[s]  at +0,8,16
    const uint32_t emptyb = sbase + SMEM_MBAR + 24;   // empty[s] at +24,32,40

    const char* blkA = reinterpret_cast<const char*>(g_A) +
                       ((size_t)blockIdx.y * T_ITERS << 14);
    const char* blkB = reinterpret_cast<const char*>(g_B) +
                       ((size_t)blockIdx.x * T_ITERS << 14);

    float acc[4][8][4];
#pragma unroll
    for (int i = 0; i < 4; i++)
#pragma unroll
        for (int j = 0; j < 8; j++)
#pragma unroll
            for (int k = 0; k < 4; k++) acc[i][j][k] = 0.f;

    // Fragment-row smem offsets / swizzle phases (loop-invariant)
    const int lr = lane & 15;
    const int lc = lane >> 4;
    uint32_t aoff[4], boff[4];
    int aph[4], bph[4];
#pragma unroll
    for (int mt = 0; mt < 4; mt++) {
        int r = wm * 64 + mt * 16 + lr;
        aoff[mt] = (uint32_t)(r * 128);
        aph[mt]  = r & 7;
    }
#pragma unroll
    for (int p = 0; p < 4; p++) {
        int r = wn * 64 + p * 16 + lr;
        boff[p] = (uint32_t)(OFF_B + r * 128);
        bph[p]  = r & 7;
    }

    if (tid == 0) {
#pragma unroll
        for (int s = 0; s < NSTAGES; s++) {
            MBAR_INIT(fullb + s * 8, 1);     // 1 arrival (expect_tx) + tx bytes
            MBAR_INIT(emptyb + s * 8, 4);    // one arrive per warp
        }
    }
    __syncthreads();   // the ONLY CTA barrier

    // Prologue: fill stages 0..2 (tiles 0..2)
    if (tid == 0) {
#pragma unroll
        for (int s = 0; s < NSTAGES; s++) {
            MBAR_EXPECT_TX(fullb + s * 8, STAGE_BYTES);
            BULK_G2S(sbase + s * STAGE_BYTES, blkA + ((size_t)s << 14),
                     TILE_BYTES, fullb + s * 8);
            BULK_G2S(sbase + s * STAGE_BYTES + OFF_B, blkB + ((size_t)s << 14),
                     TILE_BYTES, fullb + s * 8);
        }
    }

    int s = 0;          // stage of tile t
    int ph = 0, cnt = 0;  // full parity = (t/3)&1, tracked incrementally

    for (int t = 0; t < T_ITERS; t++) {
        // Producer: issue tile t+2 into stage (t+2)%3 after its readers (t-1) drain.
        if (tid == 0 && t >= 1 && t + 2 < T_ITERS) {
            int s2 = s + 2; if (s2 >= NSTAGES) s2 -= NSTAGES;
            int ep = ((t - 1) / 3) & 1;
            MBAR_WAIT(emptyb + s2 * 8, ep);
            MBAR_EXPECT_TX(fullb + s2 * 8, STAGE_BYTES);
            BULK_G2S(sbase + s2 * STAGE_BYTES, blkA + ((size_t)(t + 2) << 14),
                     TILE_BYTES, fullb + s2 * 8);
            BULK_G2S(sbase + s2 * STAGE_BYTES + OFF_B, blkB + ((size_t)(t + 2) << 14),
                     TILE_BYTES, fullb + s2 * 8);
        }

        MBAR_WAIT(fullb + s * 8, ph);
        const uint32_t rd = sbase + s * STAGE_BYTES;

        // Preload ks=0 B fragments and A(ks=0, mt=0)
        uint32_t bfrag[2][16];
        uint32_t abuf[2][4];
#pragma unroll
        for (int p = 0; p < 4; p++) {
            ldsm_x4(bfrag[0][p * 4 + 0], bfrag[0][p * 4 + 1],
                    bfrag[0][p * 4 + 2], bfrag[0][p * 4 + 3],
                    rd + boff[p] + (uint32_t)((lc ^ bph[p]) << 4));
        }
        ldsm_x4(abuf[0][0], abuf[0][1], abuf[0][2], abuf[0][3],
                rd + aoff[0] + (uint32_t)((lc ^ aph[0]) << 4));

#pragma unroll
        for (int ks = 0; ks < 4; ks++) {
            const uint32_t* bc = bfrag[ks & 1];
            if (ks < 3) {
                uint32_t* bn = bfrag[(ks + 1) & 1];
                int chunk = (ks + 1) * 2 + lc;
#pragma unroll
                for (int p = 0; p < 4; p++) {
                    ldsm_x4(bn[p * 4 + 0], bn[p * 4 + 1], bn[p * 4 + 2], bn[p * 4 + 3],
                            rd + boff[p] + (uint32_t)((chunk ^ bph[p]) << 4));
                }
            }
            int chunk = ks * 2 + lc;
#pragma unroll
            for (int mt = 0; mt < 4; mt++) {
                if (mt < 3) {
                    uint32_t* an = abuf[(mt + 1) & 1];
                    ldsm_x4(an[0], an[1], an[2], an[3],
                            rd + aoff[mt + 1] + (uint32_t)((chunk ^ aph[mt + 1]) << 4));
                } else if (ks < 3) {
                    uint32_t* an = abuf[0];
                    int nchunk = (ks + 1) * 2 + lc;
                    ldsm_x4(an[0], an[1], an[2], an[3],
                            rd + aoff[0] + (uint32_t)((nchunk ^ aph[0]) << 4));
                }
                const uint32_t* a = abuf[mt & 1];
#pragma unroll
                for (int nt = 0; nt < 8; nt++) {
                    mma_16816(acc[mt][nt], a,
                              bc[(nt >> 1) * 4 + (nt & 1)],
                              bc[(nt >> 1) * 4 + (nt & 1) + 2]);
                }
            }
        }

        if (lane == 0) MBAR_ARRIVE(emptyb + s * 8);

        if (++s == NSTAGES) s = 0;
        if (++cnt == 3) { cnt = 0; ph ^= 1; }
    }

    // Epilogue: fp16(acc) + fp16(bias) -> fp32 (reference semantics)
    const int g    = lane >> 2;
    const int tid4 = lane & 3;
#pragma unroll
    for (int mt = 0; mt < 4; mt++) {
#pragma unroll
        for (int nt = 0; nt < 8; nt++) {
            int row = bM + wm * 64 + mt * 16 + g;
            int col = bN + wn * 64 + nt * 8 + tid4 * 2;
            __half hb0 = __float2half_rn(bias[col]);
            __half hb1 = __float2half_rn(bias[col + 1]);
            float* c = acc[mt][nt];
            float2 v0;
            v0.x = __half2float(__hadd(__float2half_rn(c[0]), hb0));
            v0.y = __half2float(__hadd(__float2half_rn(c[1]), hb1));
            *reinterpret_cast<float2*>(out + (size_t)row * N_DIM + col) = v0;
            float2 v1;
            v1.x = __half2float(__hadd(__float2half_rn(c[2]), hb0));
            v1.y = __half2float(__hadd(__float2half_rn(c[3]), hb1));
            *reinterpret_cast<float2*>(out + (size_t)(row + 8) * N_DIM + col) = v1;
        }
    }
}

// ---------------------------------------------------------------------------
extern "C" void kernel_launch(void* const* d_in, const int* in_sizes, int n_in,
                              void* d_out, int out_size) {
    const float* x      = nullptr;   // 33554432 fp32
    const void*  wq     = nullptr;   // 45088768 (int8 OR int32-widened)
    const float* scales = nullptr;   // 352256 fp32
    const float* bias   = nullptr;   // 11008 fp32
    for (int i = 0; i < n_in; i++) {
        switch (in_sizes[i]) {
            case 33554432: x      = (const float*)d_in[i]; break;
            case 45088768: wq     = d_in[i];               break;
            case 352256:   scales = (const float*)d_in[i]; break;
            case 11008:    bias   = (const float*)d_in[i]; break;
            default: break;
        }
    }
    float* out = (float*)d_out;

    cudaFuncSetAttribute(gemm_kernel, cudaFuncAttributeMaxDynamicSharedMemorySize,
                         SMEM_TOTAL);

    detect_kernel<<<1, 256>>>((const int*)wq);
    {
        size_t nthr = (size_t)M_DIM * K_DIM / 8;
        convert_x_kernel<<<(unsigned)((nthr + 255) / 256), 256>>>(x);
    }
    {
        size_t nthr = (size_t)N_DIM * K_DIM / 8;
        dequant_w_kernel<<<(unsigned)((nthr + 255) / 256), 256>>>(wq, scales);
    }
    {
        dim3 grid(N_DIM / BN, M_DIM / BM);  // (86, 64)
        gemm_kernel<<<grid, THREADS, SMEM_TOTAL>>>(bias, out);
    }
}